// round 15
// baseline (speedup 1.0000x reference)
#include <cuda_runtime.h>
#include <math.h>

#define BB    128
#define NN    22
#define FF    448
#define HD    64
#define NPAIR 484
#define NUP   231
#define NUPD  253
#define PSTR  65
#define XQF   1032
#define NT    640

struct __align__(16) Smem {
    float xq[12 * XQF];            // packed row-pairs over virtual K (emb 0..63, x 64..511)
    float proj[4][24 * PSTR];      // u,v,p,q (rows 22,23 junk pad)
    float gred[2 * 4 * 384];       // stage-A cross-warp k-split partials
    float sw2s[HD * 36];
    float corrs[NPAIR], adjs[NPAIR];
    float cw2s[HD], lngs[HD], lnbs[HD], sb2s[32], sw3s[32];
    float mu[NN], istd[NN];
    int   pl[NUP], plg[NUPD];
};

__device__ __forceinline__ void fma2b(float2& d, float x0, float x1, float w) {
    float2 a = make_float2(x0, x1);
    float2 b = make_float2(w, w);
    asm("fma.rn.f32x2 %0, %1, %2, %0;"
        : "+l"(*reinterpret_cast<unsigned long long*>(&d))
        : "l"(*reinterpret_cast<const unsigned long long*>(&a)),
          "l"(*reinterpret_cast<const unsigned long long*>(&b)));
}
__device__ __forceinline__ void fma2(float2& d, const float2 a, const float2 b) {
    asm("fma.rn.f32x2 %0, %1, %2, %0;"
        : "+l"(*reinterpret_cast<unsigned long long*>(&d))
        : "l"(*reinterpret_cast<const unsigned long long*>(&a)),
          "l"(*reinterpret_cast<const unsigned long long*>(&b)));
}
__device__ __forceinline__ float warpSum(float v) {
    #pragma unroll
    for (int o = 16; o; o >>= 1) v += __shfl_xor_sync(0xffffffffu, v, o);
    return v;
}

#define BAR_AUX() asm volatile("bar.sync 2, 128;" ::: "memory")

// proven R3/R8 order
#define PSTEP(A, XV)                                              \
    fma2b(A[0], XV.x, XV.y, w0.x); fma2b(A[0], XV.z, XV.w, w1.x); \
    fma2b(A[1], XV.x, XV.y, w0.y); fma2b(A[1], XV.z, XV.w, w1.y); \
    fma2b(A[2], XV.x, XV.y, w0.z); fma2b(A[2], XV.z, XV.w, w1.z); \
    fma2b(A[3], XV.x, XV.y, w0.w); fma2b(A[3], XV.z, XV.w, w1.w);

__global__ __launch_bounds__(NT, 1)
void fused_kernel(const float* __restrict__ x,
                  const float* __restrict__ cw1, const float* __restrict__ cb1,
                  const float* __restrict__ cw2, const float* __restrict__ cb2,
                  const float* __restrict__ emb,
                  const float* __restrict__ sw1, const float* __restrict__ sb1,
                  const float* __restrict__ lng, const float* __restrict__ lnb,
                  const float* __restrict__ sw2, const float* __restrict__ sb2,
                  const float* __restrict__ sw3, const float* __restrict__ sb3,
                  const float* __restrict__ thr, const float* __restrict__ alpha_p,
                  float* __restrict__ out) {
    extern __shared__ __align__(16) char smem_raw[];
    Smem* s = reinterpret_cast<Smem*>(smem_raw);
    const int b   = blockIdx.x;
    const int tid = threadIdx.x;

    // ---------------- Phase 1: loads ----------------
    {
        const float* xb = x + (size_t)b * NN * FF;
        for (int idx = tid * 4; idx < NN * FF; idx += NT * 4) {
            int i = idx / FF;
            int k = idx - i * FF;
            float4 v = *reinterpret_cast<const float4*>(xb + idx);
            float* dst = s->xq + (i >> 1) * XQF + (64 + k) * 2 + (i & 1);
            dst[0] = v.x; dst[2] = v.y; dst[4] = v.z; dst[6] = v.w;
        }
        for (int idx = tid * 4; idx < NN * HD; idx += NT * 4) {
            int i = idx >> 6;
            int k = idx & 63;
            float4 v = *reinterpret_cast<const float4*>(emb + idx);
            float* dst = s->xq + (i >> 1) * XQF + k * 2 + (i & 1);
            dst[0] = v.x; dst[2] = v.y; dst[4] = v.z; dst[6] = v.w;
        }
        for (int idx = tid; idx < XQF; idx += NT) s->xq[11 * XQF + idx] = 0.f;  // pad pair
        if (tid < 512) {
            int c = tid >> 3, o = (tid & 7) * 4;
            *reinterpret_cast<float4*>(s->sw2s + c * 36 + o) =
                *reinterpret_cast<const float4*>(sw2 + c * 32 + o);
        }
        if (tid < HD) { s->cw2s[tid] = cw2[tid]; s->lngs[tid] = lng[tid]; s->lnbs[tid] = lnb[tid]; }
        if (tid >= HD && tid < HD + 32) { s->sb2s[tid - HD] = sb2[tid - HD]; s->sw3s[tid - HD] = sw3[tid - HD]; }
        if (tid < NPAIR) {
            s->adjs[tid] = 0.f;
            int i = tid / NN, j = tid - i * NN;
            if (i < j)  s->pl [i * (2 * NN - 1 - i) / 2 + (j - i - 1)] = (i << 5) | j;
            if (i <= j) s->plg[i * (2 * NN + 1 - i) / 2 + (j - i)]     = (i << 5) | j;
        }
    }
    __syncthreads();

    // persisted stage-A state (for post-barrier combine)
    const int lane = tid & 31;
    const int kh   = lane >> 4;
    const int c0   = (lane & 15) * 4;
    int mlocA = 0, rgA = 0, kswA = 0;
    float2 accA[3][4];
    #pragma unroll
    for (int pp = 0; pp < 3; pp++)
        #pragma unroll
        for (int cc = 0; cc < 4; cc++) accA[pp][cc] = make_float2(0.f, 0.f);

    if (tid < 512) {
        // ====== Stage A: GEMM p,q — 2 warps per (matrix, k-half), 4-way k split ======
        const int w = tid >> 5;
        mlocA = w >> 3;            // 0 -> p (m2), 1 -> q (m3)
        rgA   = (w >> 1) & 3;
        kswA  = w & 1;
        const int ks = kswA * 2 + kh;      // k quarter 0..3
        const int p0 = rgA * 3;

        const float4* xr0 = reinterpret_cast<const float4*>(s->xq + (p0 + 0) * XQF);
        const float4* xr1 = reinterpret_cast<const float4*>(s->xq + (p0 + 1) * XQF);
        const float4* xr2 = reinterpret_cast<const float4*>(s->xq + (p0 + 2) * XQF);

        // emb prefix: 8 iters of this k-quarter
        {
            const float* wA = sw1 + ((mlocA ? 64 : 0) + ks * 16) * HD + c0;
            const int xb0 = ks * 8;
            #pragma unroll 4
            for (int it = 0; it < 8; it++) {
                float4 w0 = *reinterpret_cast<const float4*>(wA);
                float4 w1 = *reinterpret_cast<const float4*>(wA + HD);
                wA += 2 * HD;
                float4 xa  = xr0[xb0 + it];
                float4 xb4 = xr1[xb0 + it];
                float4 xc  = xr2[xb0 + it];
                PSTEP(accA[0], xa);
                PSTEP(accA[1], xb4);
                PSTEP(accA[2], xc);
            }
        }
        // x segment: 56 iters, depth-2 register prefetch
        {
            const int rowB = 128 + mlocA * 448 + ks * 112;
            const float* wB = sw1 + rowB * HD + c0;
            const int xb0 = 32 + ks * 56;

            float4 w0a = *reinterpret_cast<const float4*>(wB);
            float4 w1a = *reinterpret_cast<const float4*>(wB + HD);
            float4 w0b = *reinterpret_cast<const float4*>(wB + 2 * HD);
            float4 w1b = *reinterpret_cast<const float4*>(wB + 3 * HD);

            #pragma unroll 2
            for (int it = 0; it < 54; it++) {
                float4 nw0 = *reinterpret_cast<const float4*>(wB + (2 * it + 4) * HD);
                float4 nw1 = *reinterpret_cast<const float4*>(wB + (2 * it + 5) * HD);
                float4 w0 = w0a, w1 = w1a;
                float4 xa  = xr0[xb0 + it];
                float4 xb4 = xr1[xb0 + it];
                float4 xc  = xr2[xb0 + it];
                PSTEP(accA[0], xa);
                PSTEP(accA[1], xb4);
                PSTEP(accA[2], xc);
                w0a = w0b; w1a = w1b;
                w0b = nw0; w1b = nw1;
            }
            #pragma unroll
            for (int t = 0; t < 2; t++) {
                float4 w0 = (t == 0) ? w0a : w0b;
                float4 w1 = (t == 0) ? w1a : w1b;
                int it = 54 + t;
                float4 xa  = xr0[xb0 + it];
                float4 xb4 = xr1[xb0 + it];
                float4 xc  = xr2[xb0 + it];
                PSTEP(accA[0], xa);
                PSTEP(accA[1], xb4);
                PSTEP(accA[2], xc);
            }
        }
        // in-warp reduce over kh
        #pragma unroll
        for (int pp = 0; pp < 3; pp++)
            #pragma unroll
            for (int cc = 0; cc < 4; cc++) {
                unsigned long long v = *reinterpret_cast<unsigned long long*>(&accA[pp][cc]);
                unsigned long long o = __shfl_xor_sync(0xffffffffu, v, 16);
                float2 ov = *reinterpret_cast<float2*>(&o);
                accA[pp][cc].x += ov.x;
                accA[pp][cc].y += ov.y;
            }
        // stash ksw=1 partials
        if (kswA == 1 && kh == 0) {
            float* gr = s->gred + (mlocA * 4 + rgA) * 384 + c0;
            #pragma unroll
            for (int pp = 0; pp < 3; pp++) {
                *reinterpret_cast<float4*>(gr + pp * 128) =
                    make_float4(accA[pp][0].x, accA[pp][1].x, accA[pp][2].x, accA[pp][3].x);
                *reinterpret_cast<float4*>(gr + pp * 128 + 64) =
                    make_float4(accA[pp][0].y, accA[pp][1].y, accA[pp][2].y, accA[pp][3].y);
            }
        }
    } else {
        // ====== stats + gram (warps 16-19, concurrent with stage A) ======
        const int w4 = (tid >> 5) - 16;
        for (int i = w4; i < NN; i += 4) {
            const float4* xr = reinterpret_cast<const float4*>(s->xq + (i >> 1) * XQF);
            const int par = i & 1;
            float sm = 0.f, sq = 0.f;
            for (int kq = lane; kq < 224; kq += 32) {
                float4 v = xr[32 + kq];
                float a = par ? v.y : v.x;
                float c = par ? v.w : v.z;
                sm += a + c; sq += a * a + c * c;
            }
            sm = warpSum(sm); sq = warpSum(sq);
            if (lane == 0) {
                float mm  = sm / FF;
                float var = (sq - FF * mm * mm) / (FF - 1);
                var = fmaxf(var, 0.f);
                s->mu[i]   = mm;
                s->istd[i] = 1.0f / (sqrtf(var) + 1e-8f);
            }
        }
        BAR_AUX();
        for (int pi = w4; pi < NUPD; pi += 4) {
            int code = s->plg[pi];
            int i = code >> 5, j = code & 31;
            const float4* xri = reinterpret_cast<const float4*>(s->xq + (i >> 1) * XQF);
            const float4* xrj = reinterpret_cast<const float4*>(s->xq + (j >> 1) * XQF);
            const int pari = i & 1, parj = j & 1;
            float dot = 0.f;
            for (int kq = lane; kq < 224; kq += 32) {
                float4 a = xri[32 + kq];
                float4 c = xrj[32 + kq];
                float a0 = pari ? a.y : a.x, a1 = pari ? a.w : a.z;
                float c0v = parj ? c.y : c.x, c1 = parj ? c.w : c.z;
                dot += a0 * c0v + a1 * c1;
            }
            dot = warpSum(dot);
            if (lane == 0) {
                float cv = fabsf((dot - (float)FF * s->mu[i] * s->mu[j]) * s->istd[i] * s->istd[j]) * (1.0f / FF);
                s->corrs[i * NN + j] = cv;
                s->corrs[j * NN + i] = cv;
            }
        }
    }
    __syncthreads();

    // combine stage-A halves -> proj[2], proj[3]
    if (tid < 512 && kswA == 0 && kh == 0) {
        const float* gr = s->gred + (mlocA * 4 + rgA) * 384 + c0;
        float4 bb = make_float4(0.f, 0.f, 0.f, 0.f);
        if (mlocA == 0) bb = *reinterpret_cast<const float4*>(sb1 + c0);
        float bcol[4] = {bb.x, bb.y, bb.z, bb.w};
        float* pm = s->proj[2 + mlocA];
        const int p0 = rgA * 3;
        #pragma unroll
        for (int pp = 0; pp < 3; pp++) {
            float4 ox = *reinterpret_cast<const float4*>(gr + pp * 128);
            float4 oy = *reinterpret_cast<const float4*>(gr + pp * 128 + 64);
            float oxa[4] = {ox.x, ox.y, ox.z, ox.w};
            float oya[4] = {oy.x, oy.y, oy.z, oy.w};
            int r0 = (p0 + pp) * 2;
            #pragma unroll
            for (int cc = 0; cc < 4; cc++) {
                pm[r0 * PSTR + c0 + cc]       = accA[pp][cc].x + oxa[cc] + bcol[cc];
                pm[(r0 + 1) * PSTR + c0 + cc] = accA[pp][cc].y + oya[cc] + bcol[cc];
            }
        }
    }
    __syncthreads();

    // ====== Stage B: GEMM u,v (warps 0-7, R8-verbatim) || semantic MLP (warps 8-19) ======
    if (tid < 256) {
        const int m  = tid >> 7;           // 0 -> u, 1 -> v
        const int rg = (tid >> 5) & 3;
        const int p0 = rg * 3;

        float2 acc[3][4];
        #pragma unroll
        for (int pp = 0; pp < 3; pp++)
            #pragma unroll
            for (int cc = 0; cc < 4; cc++) acc[pp][cc] = make_float2(0.f, 0.f);

        const float4* xr0 = reinterpret_cast<const float4*>(s->xq + (p0 + 0) * XQF);
        const float4* xr1 = reinterpret_cast<const float4*>(s->xq + (p0 + 1) * XQF);
        const float4* xr2 = reinterpret_cast<const float4*>(s->xq + (p0 + 2) * XQF);

        {
            const int rowB = (m == 0) ? kh * 224 : 448 + kh * 224;
            const float* wB = cw1 + rowB * HD + c0;
            const int xb0 = 32 + kh * 112;

            float4 w0a = *reinterpret_cast<const float4*>(wB);
            float4 w1a = *reinterpret_cast<const float4*>(wB + HD);
            float4 w0b = *reinterpret_cast<const float4*>(wB + 2 * HD);
            float4 w1b = *reinterpret_cast<const float4*>(wB + 3 * HD);

            #pragma unroll 2
            for (int it = 0; it < 110; it++) {
                float4 nw0 = *reinterpret_cast<const float4*>(wB + (2 * it + 4) * HD);
                float4 nw1 = *reinterpret_cast<const float4*>(wB + (2 * it + 5) * HD);
                float4 w0 = w0a, w1 = w1a;
                float4 xa  = xr0[xb0 + it];
                float4 xb4 = xr1[xb0 + it];
                float4 xc  = xr2[xb0 + it];
                PSTEP(acc[0], xa);
                PSTEP(acc[1], xb4);
                PSTEP(acc[2], xc);
                w0a = w0b; w1a = w1b;
                w0b = nw0; w1b = nw1;
            }
            #pragma unroll
            for (int t = 0; t < 2; t++) {
                float4 w0 = (t == 0) ? w0a : w0b;
                float4 w1 = (t == 0) ? w1a : w1b;
                int it = 110 + t;
                float4 xa  = xr0[xb0 + it];
                float4 xb4 = xr1[xb0 + it];
                float4 xc  = xr2[xb0 + it];
                PSTEP(acc[0], xa);
                PSTEP(acc[1], xb4);
                PSTEP(acc[2], xc);
            }
        }

        #pragma unroll
        for (int pp = 0; pp < 3; pp++)
            #pragma unroll
            for (int cc = 0; cc < 4; cc++) {
                unsigned long long v = *reinterpret_cast<unsigned long long*>(&acc[pp][cc]);
                unsigned long long o = __shfl_xor_sync(0xffffffffu, v, 16);
                float2 ov = *reinterpret_cast<float2*>(&o);
                acc[pp][cc].x += ov.x;
                acc[pp][cc].y += ov.y;
            }
        if (kh == 0) {
            float4 bb = make_float4(0.f, 0.f, 0.f, 0.f);
            if (m == 0) bb = *reinterpret_cast<const float4*>(cb1 + c0);
            float bcol[4] = {bb.x, bb.y, bb.z, bb.w};
            float* pm = s->proj[m];
            #pragma unroll
            for (int pp = 0; pp < 3; pp++) {
                int r0 = (p0 + pp) * 2;
                #pragma unroll
                for (int cc = 0; cc < 4; cc++) {
                    pm[r0 * PSTR + c0 + cc]       = acc[pp][cc].x + bcol[cc];
                    pm[(r0 + 1) * PSTR + c0 + cc] = acc[pp][cc].y + bcol[cc];
                }
            }
        }
    } else {
        // semantic MLP: thread-per-pair on 384 threads
        const int t = tid - 256;
        if (t < NUP) {
            const float tthr = 1.0f / (1.0f + __expf(-thr[0]));
            int code = s->pl[t];
            int i = code >> 5, j = code & 31;
            const float* pi = s->proj[2] + i * PSTR;
            const float* qj = s->proj[3] + j * PSTR;
            float sm = 0.f, sq = 0.f;
            #pragma unroll 4
            for (int c = 0; c < HD; c++) {
                float sv = pi[c] + qj[c];
                sm += sv; sq += sv * sv;
            }
            float muv  = sm * (1.0f / HD);
            float var  = sq * (1.0f / HD) - muv * muv;
            float rstd = rsqrtf(var + 1e-5f);
            float2 h2p[16];
            #pragma unroll
            for (int o = 0; o < 16; o++) h2p[o] = make_float2(s->sb2s[2 * o], s->sb2s[2 * o + 1]);
            #pragma unroll 2
            for (int c = 0; c < HD; c++) {
                float sv = pi[c] + qj[c];
                float h1 = fmaxf((sv - muv) * rstd * s->lngs[c] + s->lnbs[c], 0.f);
                float2 h1d = make_float2(h1, h1);
                const float4* wr = reinterpret_cast<const float4*>(s->sw2s + c * 36);
                #pragma unroll
                for (int o4 = 0; o4 < 8; o4++) {
                    float4 w = wr[o4];
                    fma2(h2p[2 * o4],     h1d, make_float2(w.x, w.y));
                    fma2(h2p[2 * o4 + 1], h1d, make_float2(w.z, w.w));
                }
            }
            float z = sb3[0];
            #pragma unroll
            for (int o = 0; o < 16; o++) {
                z += fmaxf(h2p[o].x, 0.f) * s->sw3s[2 * o];
                z += fmaxf(h2p[o].y, 0.f) * s->sw3s[2 * o + 1];
            }
            float ws  = 1.0f / (1.0f + __expf(-z));
            float val = (ws > tthr) ? ws : 0.f;
            s->adjs[i * NN + j] = val;
            s->adjs[j * NN + i] = val;
        }
    }
    __syncthreads();

    // ====== Stage C: corr MLP + fuse + store ======
    if (tid < NPAIR) {
        const float alpha = 1.0f / (1.0f + __expf(-alpha_p[0]));
        const float cb2v  = cb2[0];
        int i = tid / NN, j = tid - i * NN;
        const float* ui = s->proj[0] + i * PSTR;
        const float* vj = s->proj[1] + j * PSTR;
        float z = cb2v;
        #pragma unroll 4
        for (int c = 0; c < HD; c++)
            z += fmaxf(ui[c] + vj[c], 0.f) * s->cw2s[c];
        float wc = 1.0f / (1.0f + __expf(-z));
        float eye = (i == j) ? 1.0f : 0.0f;
        out[(size_t)b * NPAIR + tid] =
            alpha * s->corrs[tid] * wc + (1.0f - alpha) * s->adjs[tid] + eye;
    }
}

extern "C" void kernel_launch(void* const* d_in, const int* in_sizes, int n_in,
                              void* d_out, int out_size) {
    const float* x       = (const float*)d_in[0];
    const float* cw1     = (const float*)d_in[1];
    const float* cb1     = (const float*)d_in[2];
    const float* cw2     = (const float*)d_in[3];
    const float* cb2     = (const float*)d_in[4];
    const float* emb     = (const float*)d_in[5];
    const float* sw1     = (const float*)d_in[6];
    const float* sb1     = (const float*)d_in[7];
    const float* ln_g    = (const float*)d_in[8];
    const float* ln_b    = (const float*)d_in[9];
    const float* sw2     = (const float*)d_in[10];
    const float* sb2     = (const float*)d_in[11];
    const float* sw3     = (const float*)d_in[12];
    const float* sb3     = (const float*)d_in[13];
    const float* thr     = (const float*)d_in[14];
    const float* alpha_p = (const float*)d_in[15];
    float* out = (float*)d_out;

    static bool attr_set = false;
    if (!attr_set) {
        cudaFuncSetAttribute(fused_kernel, cudaFuncAttributeMaxDynamicSharedMemorySize,
                             (int)sizeof(Smem));
        attr_set = true;
    }
    fused_kernel<<<BB, NT, sizeof(Smem)>>>(x, cw1, cb1, cw2, cb2, emb, sw1, sb1,
                                           ln_g, ln_b, sw2, sb2, sw3, sb3, thr, alpha_p, out);
}

// round 16
// speedup vs baseline: 1.1134x; 1.1134x over previous
#include <cuda_runtime.h>
#include <math.h>

#define BB    128
#define NN    22
#define FF    448
#define HD    64
#define NPAIR 484
#define NUP   231
#define NUPD  253
#define PSTR  65
#define XQF   1032
#define NT    640

struct __align__(16) Smem {
    float xq[12 * XQF];            // packed row-pairs over virtual K (emb 0..63, x 64..511)
    float proj[4][24 * PSTR];      // u,v,p,q (rows 22,23 junk pad)
    float gred[2 * 4 * 384];       // cross-warp k-split partials (reused A then B)
    float sw2s[HD * 36];
    float corrs[NPAIR], adjs[NPAIR];
    float cw2s[HD], lngs[HD], lnbs[HD], sb2s[32], sw3s[32];
    float mu[NN], istd[NN];
    int   pl[NUP], plg[NUPD];
};

__device__ __forceinline__ void fma2b(float2& d, float x0, float x1, float w) {
    float2 a = make_float2(x0, x1);
    float2 b = make_float2(w, w);
    asm("fma.rn.f32x2 %0, %1, %2, %0;"
        : "+l"(*reinterpret_cast<unsigned long long*>(&d))
        : "l"(*reinterpret_cast<const unsigned long long*>(&a)),
          "l"(*reinterpret_cast<const unsigned long long*>(&b)));
}
__device__ __forceinline__ void fma2(float2& d, const float2 a, const float2 b) {
    asm("fma.rn.f32x2 %0, %1, %2, %0;"
        : "+l"(*reinterpret_cast<unsigned long long*>(&d))
        : "l"(*reinterpret_cast<const unsigned long long*>(&a)),
          "l"(*reinterpret_cast<const unsigned long long*>(&b)));
}
__device__ __forceinline__ float warpSum(float v) {
    #pragma unroll
    for (int o = 16; o; o >>= 1) v += __shfl_xor_sync(0xffffffffu, v, o);
    return v;
}

#define BAR_GEMM() asm volatile("bar.sync 1, 512;" ::: "memory")
#define BAR_AUX()  asm volatile("bar.sync 2, 128;" ::: "memory")

// proven R3/R8 order
#define PSTEP(A, XV)                                              \
    fma2b(A[0], XV.x, XV.y, w0.x); fma2b(A[0], XV.z, XV.w, w1.x); \
    fma2b(A[1], XV.x, XV.y, w0.y); fma2b(A[1], XV.z, XV.w, w1.y); \
    fma2b(A[2], XV.x, XV.y, w0.z); fma2b(A[2], XV.z, XV.w, w1.z); \
    fma2b(A[3], XV.x, XV.y, w0.w); fma2b(A[3], XV.z, XV.w, w1.w);

__global__ __launch_bounds__(NT, 1)
void fused_kernel(const float* __restrict__ x,
                  const float* __restrict__ cw1, const float* __restrict__ cb1,
                  const float* __restrict__ cw2, const float* __restrict__ cb2,
                  const float* __restrict__ emb,
                  const float* __restrict__ sw1, const float* __restrict__ sb1,
                  const float* __restrict__ lng, const float* __restrict__ lnb,
                  const float* __restrict__ sw2, const float* __restrict__ sb2,
                  const float* __restrict__ sw3, const float* __restrict__ sb3,
                  const float* __restrict__ thr, const float* __restrict__ alpha_p,
                  float* __restrict__ out) {
    extern __shared__ __align__(16) char smem_raw[];
    Smem* s = reinterpret_cast<Smem*>(smem_raw);
    const int b   = blockIdx.x;
    const int tid = threadIdx.x;

    // ---------------- Phase 1: loads ----------------
    {
        const float* xb = x + (size_t)b * NN * FF;
        for (int idx = tid * 4; idx < NN * FF; idx += NT * 4) {
            int i = idx / FF;
            int k = idx - i * FF;
            float4 v = *reinterpret_cast<const float4*>(xb + idx);
            float* dst = s->xq + (i >> 1) * XQF + (64 + k) * 2 + (i & 1);
            dst[0] = v.x; dst[2] = v.y; dst[4] = v.z; dst[6] = v.w;
        }
        for (int idx = tid * 4; idx < NN * HD; idx += NT * 4) {
            int i = idx >> 6;
            int k = idx & 63;
            float4 v = *reinterpret_cast<const float4*>(emb + idx);
            float* dst = s->xq + (i >> 1) * XQF + k * 2 + (i & 1);
            dst[0] = v.x; dst[2] = v.y; dst[4] = v.z; dst[6] = v.w;
        }
        for (int idx = tid; idx < XQF; idx += NT) s->xq[11 * XQF + idx] = 0.f;  // pad pair
        if (tid < 512) {
            int c = tid >> 3, o = (tid & 7) * 4;
            *reinterpret_cast<float4*>(s->sw2s + c * 36 + o) =
                *reinterpret_cast<const float4*>(sw2 + c * 32 + o);
        }
        if (tid < HD) { s->cw2s[tid] = cw2[tid]; s->lngs[tid] = lng[tid]; s->lnbs[tid] = lnb[tid]; }
        if (tid >= HD && tid < HD + 32) { s->sb2s[tid - HD] = sb2[tid - HD]; s->sw3s[tid - HD] = sw3[tid - HD]; }
        if (tid < NPAIR) {
            s->adjs[tid] = 0.f;
            int i = tid / NN, j = tid - i * NN;
            if (i < j)  s->pl [i * (2 * NN - 1 - i) / 2 + (j - i - 1)] = (i << 5) | j;
            if (i <= j) s->plg[i * (2 * NN + 1 - i) / 2 + (j - i)]     = (i << 5) | j;
        }
    }
    __syncthreads();

    const int lane = tid & 31;
    const int kh   = lane >> 4;
    const int c0   = (lane & 15) * 4;

    if (tid < 512) {
        // ====================== GEMM warps 0-15 ======================
        const int w    = tid >> 5;
        const int mloc = w >> 3;          // stage A: 0->p,1->q ; stage B: 0->u,1->v
        const int rg   = (w >> 1) & 3;
        const int ksw  = w & 1;
        const int ks   = ksw * 2 + kh;    // k quarter 0..3
        const int p0   = rg * 3;

        const float4* xr0 = reinterpret_cast<const float4*>(s->xq + (p0 + 0) * XQF);
        const float4* xr1 = reinterpret_cast<const float4*>(s->xq + (p0 + 1) * XQF);
        const float4* xr2 = reinterpret_cast<const float4*>(s->xq + (p0 + 2) * XQF);

        // ---------- Stage A: p,q (sw1), k-split 4 ----------
        float2 acc[3][4];
        #pragma unroll
        for (int pp = 0; pp < 3; pp++)
            #pragma unroll
            for (int cc = 0; cc < 4; cc++) acc[pp][cc] = make_float2(0.f, 0.f);

        // emb prefix: 8 float4-iters of this k-quarter
        {
            const float* wA = sw1 + ((mloc ? 64 : 0) + ks * 16) * HD + c0;
            const int xb0 = ks * 8;
            #pragma unroll 4
            for (int it = 0; it < 8; it++) {
                float4 w0 = *reinterpret_cast<const float4*>(wA);
                float4 w1 = *reinterpret_cast<const float4*>(wA + HD);
                wA += 2 * HD;
                float4 xa  = xr0[xb0 + it];
                float4 xb4 = xr1[xb0 + it];
                float4 xc  = xr2[xb0 + it];
                PSTEP(acc[0], xa);
                PSTEP(acc[1], xb4);
                PSTEP(acc[2], xc);
            }
        }
        // x segment: 56 iters, depth-2 register prefetch
        {
            const int rowB = 128 + mloc * 448 + ks * 112;
            const float* wB = sw1 + rowB * HD + c0;
            const int xb0 = 32 + ks * 56;

            float4 w0a = *reinterpret_cast<const float4*>(wB);
            float4 w1a = *reinterpret_cast<const float4*>(wB + HD);
            float4 w0b = *reinterpret_cast<const float4*>(wB + 2 * HD);
            float4 w1b = *reinterpret_cast<const float4*>(wB + 3 * HD);

            #pragma unroll 2
            for (int it = 0; it < 54; it++) {
                float4 nw0 = *reinterpret_cast<const float4*>(wB + (2 * it + 4) * HD);
                float4 nw1 = *reinterpret_cast<const float4*>(wB + (2 * it + 5) * HD);
                float4 w0 = w0a, w1 = w1a;
                float4 xa  = xr0[xb0 + it];
                float4 xb4 = xr1[xb0 + it];
                float4 xc  = xr2[xb0 + it];
                PSTEP(acc[0], xa);
                PSTEP(acc[1], xb4);
                PSTEP(acc[2], xc);
                w0a = w0b; w1a = w1b;
                w0b = nw0; w1b = nw1;
            }
            #pragma unroll
            for (int t = 0; t < 2; t++) {
                float4 w0 = (t == 0) ? w0a : w0b;
                float4 w1 = (t == 0) ? w1a : w1b;
                int it = 54 + t;
                float4 xa  = xr0[xb0 + it];
                float4 xb4 = xr1[xb0 + it];
                float4 xc  = xr2[xb0 + it];
                PSTEP(acc[0], xa);
                PSTEP(acc[1], xb4);
                PSTEP(acc[2], xc);
            }
        }
        // in-warp reduce over kh
        #pragma unroll
        for (int pp = 0; pp < 3; pp++)
            #pragma unroll
            for (int cc = 0; cc < 4; cc++) {
                unsigned long long v = *reinterpret_cast<unsigned long long*>(&acc[pp][cc]);
                unsigned long long o = __shfl_xor_sync(0xffffffffu, v, 16);
                float2 ov = *reinterpret_cast<float2*>(&o);
                acc[pp][cc].x += ov.x;
                acc[pp][cc].y += ov.y;
            }
        if (ksw == 1 && kh == 0) {
            float* gr = s->gred + (mloc * 4 + rg) * 384 + c0;
            #pragma unroll
            for (int pp = 0; pp < 3; pp++) {
                *reinterpret_cast<float4*>(gr + pp * 128) =
                    make_float4(acc[pp][0].x, acc[pp][1].x, acc[pp][2].x, acc[pp][3].x);
                *reinterpret_cast<float4*>(gr + pp * 128 + 64) =
                    make_float4(acc[pp][0].y, acc[pp][1].y, acc[pp][2].y, acc[pp][3].y);
            }
        }
        BAR_GEMM();
        if (ksw == 0 && kh == 0) {
            const float* gr = s->gred + (mloc * 4 + rg) * 384 + c0;
            float4 bb = make_float4(0.f, 0.f, 0.f, 0.f);
            if (mloc == 0) bb = *reinterpret_cast<const float4*>(sb1 + c0);
            float bcol[4] = {bb.x, bb.y, bb.z, bb.w};
            float* pm = s->proj[2 + mloc];
            #pragma unroll
            for (int pp = 0; pp < 3; pp++) {
                float4 ox = *reinterpret_cast<const float4*>(gr + pp * 128);
                float4 oy = *reinterpret_cast<const float4*>(gr + pp * 128 + 64);
                float oxa[4] = {ox.x, ox.y, ox.z, ox.w};
                float oya[4] = {oy.x, oy.y, oy.z, oy.w};
                int r0 = (p0 + pp) * 2;
                #pragma unroll
                for (int cc = 0; cc < 4; cc++) {
                    pm[r0 * PSTR + c0 + cc]       = acc[pp][cc].x + oxa[cc] + bcol[cc];
                    pm[(r0 + 1) * PSTR + c0 + cc] = acc[pp][cc].y + oya[cc] + bcol[cc];
                }
            }
        }
        BAR_GEMM();

        // ---------- Stage B: u,v (cw1), k-split 4, no emb prefix ----------
        #pragma unroll
        for (int pp = 0; pp < 3; pp++)
            #pragma unroll
            for (int cc = 0; cc < 4; cc++) acc[pp][cc] = make_float2(0.f, 0.f);
        {
            const int rowB = mloc * 448 + ks * 112;
            const float* wB = cw1 + rowB * HD + c0;
            const int xb0 = 32 + ks * 56;

            float4 w0a = *reinterpret_cast<const float4*>(wB);
            float4 w1a = *reinterpret_cast<const float4*>(wB + HD);
            float4 w0b = *reinterpret_cast<const float4*>(wB + 2 * HD);
            float4 w1b = *reinterpret_cast<const float4*>(wB + 3 * HD);

            #pragma unroll 2
            for (int it = 0; it < 54; it++) {
                float4 nw0 = *reinterpret_cast<const float4*>(wB + (2 * it + 4) * HD);
                float4 nw1 = *reinterpret_cast<const float4*>(wB + (2 * it + 5) * HD);
                float4 w0 = w0a, w1 = w1a;
                float4 xa  = xr0[xb0 + it];
                float4 xb4 = xr1[xb0 + it];
                float4 xc  = xr2[xb0 + it];
                PSTEP(acc[0], xa);
                PSTEP(acc[1], xb4);
                PSTEP(acc[2], xc);
                w0a = w0b; w1a = w1b;
                w0b = nw0; w1b = nw1;
            }
            #pragma unroll
            for (int t = 0; t < 2; t++) {
                float4 w0 = (t == 0) ? w0a : w0b;
                float4 w1 = (t == 0) ? w1a : w1b;
                int it = 54 + t;
                float4 xa  = xr0[xb0 + it];
                float4 xb4 = xr1[xb0 + it];
                float4 xc  = xr2[xb0 + it];
                PSTEP(acc[0], xa);
                PSTEP(acc[1], xb4);
                PSTEP(acc[2], xc);
            }
        }
        #pragma unroll
        for (int pp = 0; pp < 3; pp++)
            #pragma unroll
            for (int cc = 0; cc < 4; cc++) {
                unsigned long long v = *reinterpret_cast<unsigned long long*>(&acc[pp][cc]);
                unsigned long long o = __shfl_xor_sync(0xffffffffu, v, 16);
                float2 ov = *reinterpret_cast<float2*>(&o);
                acc[pp][cc].x += ov.x;
                acc[pp][cc].y += ov.y;
            }
        if (ksw == 1 && kh == 0) {
            float* gr = s->gred + (mloc * 4 + rg) * 384 + c0;
            #pragma unroll
            for (int pp = 0; pp < 3; pp++) {
                *reinterpret_cast<float4*>(gr + pp * 128) =
                    make_float4(acc[pp][0].x, acc[pp][1].x, acc[pp][2].x, acc[pp][3].x);
                *reinterpret_cast<float4*>(gr + pp * 128 + 64) =
                    make_float4(acc[pp][0].y, acc[pp][1].y, acc[pp][2].y, acc[pp][3].y);
            }
        }
        BAR_GEMM();
        if (ksw == 0 && kh == 0) {
            const float* gr = s->gred + (mloc * 4 + rg) * 384 + c0;
            float4 bb = make_float4(0.f, 0.f, 0.f, 0.f);
            if (mloc == 0) bb = *reinterpret_cast<const float4*>(cb1 + c0);
            float bcol[4] = {bb.x, bb.y, bb.z, bb.w};
            float* pm = s->proj[mloc];
            #pragma unroll
            for (int pp = 0; pp < 3; pp++) {
                float4 ox = *reinterpret_cast<const float4*>(gr + pp * 128);
                float4 oy = *reinterpret_cast<const float4*>(gr + pp * 128 + 64);
                float oxa[4] = {ox.x, ox.y, ox.z, ox.w};
                float oya[4] = {oy.x, oy.y, oy.z, oy.w};
                int r0 = (p0 + pp) * 2;
                #pragma unroll
                for (int cc = 0; cc < 4; cc++) {
                    pm[r0 * PSTR + c0 + cc]       = acc[pp][cc].x + oxa[cc] + bcol[cc];
                    pm[(r0 + 1) * PSTR + c0 + cc] = acc[pp][cc].y + oya[cc] + bcol[cc];
                }
            }
        }
        BAR_GEMM();

        // ---------- Semantic MLP (tid<231, p/q ready since stage-A combine) ----------
        if (tid < NUP) {
            const float tthr = 1.0f / (1.0f + __expf(-thr[0]));
            int code = s->pl[tid];
            int i = code >> 5, j = code & 31;
            const float* pi = s->proj[2] + i * PSTR;
            const float* qj = s->proj[3] + j * PSTR;
            float sm = 0.f, sq = 0.f;
            #pragma unroll 4
            for (int c = 0; c < HD; c++) {
                float sv = pi[c] + qj[c];
                sm += sv; sq += sv * sv;
            }
            float muv  = sm * (1.0f / HD);
            float var  = sq * (1.0f / HD) - muv * muv;
            float rstd = rsqrtf(var + 1e-5f);
            float2 h2p[16];
            #pragma unroll
            for (int o = 0; o < 16; o++) h2p[o] = make_float2(s->sb2s[2 * o], s->sb2s[2 * o + 1]);
            #pragma unroll 2
            for (int c = 0; c < HD; c++) {
                float sv = pi[c] + qj[c];
                float h1 = fmaxf((sv - muv) * rstd * s->lngs[c] + s->lnbs[c], 0.f);
                float2 h1d = make_float2(h1, h1);
                const float4* wr = reinterpret_cast<const float4*>(s->sw2s + c * 36);
                #pragma unroll
                for (int o4 = 0; o4 < 8; o4++) {
                    float4 w = wr[o4];
                    fma2(h2p[2 * o4],     h1d, make_float2(w.x, w.y));
                    fma2(h2p[2 * o4 + 1], h1d, make_float2(w.z, w.w));
                }
            }
            float z = sb3[0];
            #pragma unroll
            for (int o = 0; o < 16; o++) {
                z += fmaxf(h2p[o].x, 0.f) * s->sw3s[2 * o];
                z += fmaxf(h2p[o].y, 0.f) * s->sw3s[2 * o + 1];
            }
            float ws  = 1.0f / (1.0f + __expf(-z));
            float val = (ws > tthr) ? ws : 0.f;
            s->adjs[i * NN + j] = val;
            s->adjs[j * NN + i] = val;
        }
    } else {
        // ====================== aux warps 16-19: stats + gram (free-running) ======================
        const int w4 = (tid >> 5) - 16;
        for (int i = w4; i < NN; i += 4) {
            const float4* xr = reinterpret_cast<const float4*>(s->xq + (i >> 1) * XQF);
            const int par = i & 1;
            float sm = 0.f, sq = 0.f;
            for (int kq = lane; kq < 224; kq += 32) {
                float4 v = xr[32 + kq];
                float a = par ? v.y : v.x;
                float c = par ? v.w : v.z;
                sm += a + c; sq += a * a + c * c;
            }
            sm = warpSum(sm); sq = warpSum(sq);
            if (lane == 0) {
                float mm  = sm / FF;
                float var = (sq - FF * mm * mm) / (FF - 1);
                var = fmaxf(var, 0.f);
                s->mu[i]   = mm;
                s->istd[i] = 1.0f / (sqrtf(var) + 1e-8f);
            }
        }
        BAR_AUX();
        for (int pi = w4; pi < NUPD; pi += 4) {
            int code = s->plg[pi];
            int i = code >> 5, j = code & 31;
            const float4* xri = reinterpret_cast<const float4*>(s->xq + (i >> 1) * XQF);
            const float4* xrj = reinterpret_cast<const float4*>(s->xq + (j >> 1) * XQF);
            const int pari = i & 1, parj = j & 1;
            float dot = 0.f;
            for (int kq = lane; kq < 224; kq += 32) {
                float4 a = xri[32 + kq];
                float4 c = xrj[32 + kq];
                float a0 = pari ? a.y : a.x, a1 = pari ? a.w : a.z;
                float c0v = parj ? c.y : c.x, c1 = parj ? c.w : c.z;
                dot += a0 * c0v + a1 * c1;
            }
            dot = warpSum(dot);
            if (lane == 0) {
                float cv = fabsf((dot - (float)FF * s->mu[i] * s->mu[j]) * s->istd[i] * s->istd[j]) * (1.0f / FF);
                s->corrs[i * NN + j] = cv;
                s->corrs[j * NN + i] = cv;
            }
        }
    }
    __syncthreads();

    // ====================== final: corr MLP + fuse + store ======================
    if (tid < NPAIR) {
        const float alpha = 1.0f / (1.0f + __expf(-alpha_p[0]));
        const float cb2v  = cb2[0];
        int i = tid / NN, j = tid - i * NN;
        const float* ui = s->proj[0] + i * PSTR;
        const float* vj = s->proj[1] + j * PSTR;
        float z = cb2v;
        #pragma unroll 4
        for (int c = 0; c < HD; c++)
            z += fmaxf(ui[c] + vj[c], 0.f) * s->cw2s[c];
        float wc = 1.0f / (1.0f + __expf(-z));
        float eye = (i == j) ? 1.0f : 0.0f;
        out[(size_t)b * NPAIR + tid] =
            alpha * s->corrs[tid] * wc + (1.0f - alpha) * s->adjs[tid] + eye;
    }
}

extern "C" void kernel_launch(void* const* d_in, const int* in_sizes, int n_in,
                              void* d_out, int out_size) {
    const float* x       = (const float*)d_in[0];
    const float* cw1     = (const float*)d_in[1];
    const float* cb1     = (const float*)d_in[2];
    const float* cw2     = (const float*)d_in[3];
    const float* cb2     = (const float*)d_in[4];
    const float* emb     = (const float*)d_in[5];
    const float* sw1     = (const float*)d_in[6];
    const float* sb1     = (const float*)d_in[7];
    const float* ln_g    = (const float*)d_in[8];
    const float* ln_b    = (const float*)d_in[9];
    const float* sw2     = (const float*)d_in[10];
    const float* sb2     = (const float*)d_in[11];
    const float* sw3     = (const float*)d_in[12];
    const float* sb3     = (const float*)d_in[13];
    const float* thr     = (const float*)d_in[14];
    const float* alpha_p = (const float*)d_in[15];
    float* out = (float*)d_out;

    static bool attr_set = false;
    if (!attr_set) {
        cudaFuncSetAttribute(fused_kernel, cudaFuncAttributeMaxDynamicSharedMemorySize,
                             (int)sizeof(Smem));
        attr_set = true;
    }
    fused_kernel<<<BB, NT, sizeof(Smem)>>>(x, cw1, cb1, cw2, cb2, emb, sw1, sb1,
                                           ln_g, ln_b, sw2, sb2, sw3, sb3, thr, alpha_p, out);
}

// round 17
// speedup vs baseline: 1.4573x; 1.3089x over previous
#include <cuda_runtime.h>
#include <math.h>

#define BB    128
#define NN    22
#define FF    448
#define HD    64
#define NPAIR 484
#define NUP   231
#define NUPD  253
#define PSTR  65
#define XQF   1032
#define NT    640

struct __align__(16) Smem {
    float xq[12 * XQF];            // packed row-pairs over virtual K (emb 0..63, x 64..511)
    float proj[4][24 * PSTR];      // u,v,p,q (rows 22,23 junk pad)
    float gred[2 * 4 * 384];       // cross-warp k-split partials (reused A then B)
    float sw2s[HD * 36];
    float corrs[NPAIR], adjs[NPAIR];
    float cw2s[HD], lngs[HD], lnbs[HD], sb2s[32], sw3s[32];
    float mu[NN], istd[NN];
    int   pl[NUP], plg[NUPD];
};

__device__ __forceinline__ void fma2b(float2& d, float x0, float x1, float w) {
    float2 a = make_float2(x0, x1);
    float2 b = make_float2(w, w);
    asm("fma.rn.f32x2 %0, %1, %2, %0;"
        : "+l"(*reinterpret_cast<unsigned long long*>(&d))
        : "l"(*reinterpret_cast<const unsigned long long*>(&a)),
          "l"(*reinterpret_cast<const unsigned long long*>(&b)));
}
__device__ __forceinline__ void fma2(float2& d, const float2 a, const float2 b) {
    asm("fma.rn.f32x2 %0, %1, %2, %0;"
        : "+l"(*reinterpret_cast<unsigned long long*>(&d))
        : "l"(*reinterpret_cast<const unsigned long long*>(&a)),
          "l"(*reinterpret_cast<const unsigned long long*>(&b)));
}
__device__ __forceinline__ float warpSum(float v) {
    #pragma unroll
    for (int o = 16; o; o >>= 1) v += __shfl_xor_sync(0xffffffffu, v, o);
    return v;
}

#define BAR_GEMM() asm volatile("bar.sync 1, 512;" ::: "memory")
#define BAR_AUX()  asm volatile("bar.sync 2, 128;" ::: "memory")

// proven R3/R8 order
#define PSTEP(A, XV)                                              \
    fma2b(A[0], XV.x, XV.y, w0.x); fma2b(A[0], XV.z, XV.w, w1.x); \
    fma2b(A[1], XV.x, XV.y, w0.y); fma2b(A[1], XV.z, XV.w, w1.y); \
    fma2b(A[2], XV.x, XV.y, w0.z); fma2b(A[2], XV.z, XV.w, w1.z); \
    fma2b(A[3], XV.x, XV.y, w0.w); fma2b(A[3], XV.z, XV.w, w1.w);

__global__ __launch_bounds__(NT, 1)
void fused_kernel(const float* __restrict__ x,
                  const float* __restrict__ cw1, const float* __restrict__ cb1,
                  const float* __restrict__ cw2, const float* __restrict__ cb2,
                  const float* __restrict__ emb,
                  const float* __restrict__ sw1, const float* __restrict__ sb1,
                  const float* __restrict__ lng, const float* __restrict__ lnb,
                  const float* __restrict__ sw2, const float* __restrict__ sb2,
                  const float* __restrict__ sw3, const float* __restrict__ sb3,
                  const float* __restrict__ thr, const float* __restrict__ alpha_p,
                  float* __restrict__ out) {
    extern __shared__ __align__(16) char smem_raw[];
    Smem* s = reinterpret_cast<Smem*>(smem_raw);
    const int b   = blockIdx.x;
    const int tid = threadIdx.x;

    // ---------------- Phase 1: loads ----------------
    {
        const float* xb = x + (size_t)b * NN * FF;
        for (int idx = tid * 4; idx < NN * FF; idx += NT * 4) {
            int i = idx / FF;
            int k = idx - i * FF;
            float4 v = *reinterpret_cast<const float4*>(xb + idx);
            float* dst = s->xq + (i >> 1) * XQF + (64 + k) * 2 + (i & 1);
            dst[0] = v.x; dst[2] = v.y; dst[4] = v.z; dst[6] = v.w;
        }
        for (int idx = tid * 4; idx < NN * HD; idx += NT * 4) {
            int i = idx >> 6;
            int k = idx & 63;
            float4 v = *reinterpret_cast<const float4*>(emb + idx);
            float* dst = s->xq + (i >> 1) * XQF + k * 2 + (i & 1);
            dst[0] = v.x; dst[2] = v.y; dst[4] = v.z; dst[6] = v.w;
        }
        for (int idx = tid; idx < XQF; idx += NT) s->xq[11 * XQF + idx] = 0.f;  // pad pair
        if (tid < 512) {
            int c = tid >> 3, o = (tid & 7) * 4;
            *reinterpret_cast<float4*>(s->sw2s + c * 36 + o) =
                *reinterpret_cast<const float4*>(sw2 + c * 32 + o);
        }
        if (tid < HD) { s->cw2s[tid] = cw2[tid]; s->lngs[tid] = lng[tid]; s->lnbs[tid] = lnb[tid]; }
        if (tid >= HD && tid < HD + 32) { s->sb2s[tid - HD] = sb2[tid - HD]; s->sw3s[tid - HD] = sw3[tid - HD]; }
        if (tid < NPAIR) {
            s->adjs[tid] = 0.f;
            int i = tid / NN, j = tid - i * NN;
            if (i < j)  s->pl [i * (2 * NN - 1 - i) / 2 + (j - i - 1)] = (i << 5) | j;
            if (i <= j) s->plg[i * (2 * NN + 1 - i) / 2 + (j - i)]     = (i << 5) | j;
        }
    }
    __syncthreads();

    const int lane = tid & 31;
    const int kh   = lane >> 4;
    const int c0   = (lane & 15) * 4;

    if (tid < 512) {
        // ====================== GEMM warps 0-15 ======================
        const int w    = tid >> 5;
        const int mloc = w >> 3;          // stage A: 0->p,1->q ; stage B: 0->u,1->v
        const int rg   = (w >> 1) & 3;
        const int ksw  = w & 1;
        const int ks   = ksw * 2 + kh;    // k quarter 0..3
        const int p0   = rg * 3;

        const float4* xr0 = reinterpret_cast<const float4*>(s->xq + (p0 + 0) * XQF);
        const float4* xr1 = reinterpret_cast<const float4*>(s->xq + (p0 + 1) * XQF);
        const float4* xr2 = reinterpret_cast<const float4*>(s->xq + (p0 + 2) * XQF);

        // ---------- Stage A: p,q (sw1), k-split 4 ----------
        float2 acc[3][4];
        #pragma unroll
        for (int pp = 0; pp < 3; pp++)
            #pragma unroll
            for (int cc = 0; cc < 4; cc++) acc[pp][cc] = make_float2(0.f, 0.f);

        // emb prefix: 8 float4-iters of this k-quarter
        {
            const float* wA = sw1 + ((mloc ? 64 : 0) + ks * 16) * HD + c0;
            const int xb0 = ks * 8;
            #pragma unroll 4
            for (int it = 0; it < 8; it++) {
                float4 w0 = *reinterpret_cast<const float4*>(wA);
                float4 w1 = *reinterpret_cast<const float4*>(wA + HD);
                wA += 2 * HD;
                float4 xa  = xr0[xb0 + it];
                float4 xb4 = xr1[xb0 + it];
                float4 xc  = xr2[xb0 + it];
                PSTEP(acc[0], xa);
                PSTEP(acc[1], xb4);
                PSTEP(acc[2], xc);
            }
        }
        // x segment: 56 iters, depth-2 register prefetch
        {
            const int rowB = 128 + mloc * 448 + ks * 112;
            const float* wB = sw1 + rowB * HD + c0;
            const int xb0 = 32 + ks * 56;

            float4 w0a = *reinterpret_cast<const float4*>(wB);
            float4 w1a = *reinterpret_cast<const float4*>(wB + HD);
            float4 w0b = *reinterpret_cast<const float4*>(wB + 2 * HD);
            float4 w1b = *reinterpret_cast<const float4*>(wB + 3 * HD);

            #pragma unroll 2
            for (int it = 0; it < 54; it++) {
                float4 nw0 = *reinterpret_cast<const float4*>(wB + (2 * it + 4) * HD);
                float4 nw1 = *reinterpret_cast<const float4*>(wB + (2 * it + 5) * HD);
                float4 w0 = w0a, w1 = w1a;
                float4 xa  = xr0[xb0 + it];
                float4 xb4 = xr1[xb0 + it];
                float4 xc  = xr2[xb0 + it];
                PSTEP(acc[0], xa);
                PSTEP(acc[1], xb4);
                PSTEP(acc[2], xc);
                w0a = w0b; w1a = w1b;
                w0b = nw0; w1b = nw1;
            }
            #pragma unroll
            for (int t = 0; t < 2; t++) {
                float4 w0 = (t == 0) ? w0a : w0b;
                float4 w1 = (t == 0) ? w1a : w1b;
                int it = 54 + t;
                float4 xa  = xr0[xb0 + it];
                float4 xb4 = xr1[xb0 + it];
                float4 xc  = xr2[xb0 + it];
                PSTEP(acc[0], xa);
                PSTEP(acc[1], xb4);
                PSTEP(acc[2], xc);
            }
        }
        // in-warp reduce over kh
        #pragma unroll
        for (int pp = 0; pp < 3; pp++)
            #pragma unroll
            for (int cc = 0; cc < 4; cc++) {
                unsigned long long v = *reinterpret_cast<unsigned long long*>(&acc[pp][cc]);
                unsigned long long o = __shfl_xor_sync(0xffffffffu, v, 16);
                float2 ov = *reinterpret_cast<float2*>(&o);
                acc[pp][cc].x += ov.x;
                acc[pp][cc].y += ov.y;
            }
        if (ksw == 1 && kh == 0) {
            float* gr = s->gred + (mloc * 4 + rg) * 384 + c0;
            #pragma unroll
            for (int pp = 0; pp < 3; pp++) {
                *reinterpret_cast<float4*>(gr + pp * 128) =
                    make_float4(acc[pp][0].x, acc[pp][1].x, acc[pp][2].x, acc[pp][3].x);
                *reinterpret_cast<float4*>(gr + pp * 128 + 64) =
                    make_float4(acc[pp][0].y, acc[pp][1].y, acc[pp][2].y, acc[pp][3].y);
            }
        }
        BAR_GEMM();
        if (ksw == 0 && kh == 0) {
            const float* gr = s->gred + (mloc * 4 + rg) * 384 + c0;
            float4 bb = make_float4(0.f, 0.f, 0.f, 0.f);
            if (mloc == 0) bb = *reinterpret_cast<const float4*>(sb1 + c0);
            float bcol[4] = {bb.x, bb.y, bb.z, bb.w};
            float* pm = s->proj[2 + mloc];
            #pragma unroll
            for (int pp = 0; pp < 3; pp++) {
                float4 ox = *reinterpret_cast<const float4*>(gr + pp * 128);
                float4 oy = *reinterpret_cast<const float4*>(gr + pp * 128 + 64);
                float oxa[4] = {ox.x, ox.y, ox.z, ox.w};
                float oya[4] = {oy.x, oy.y, oy.z, oy.w};
                int r0 = (p0 + pp) * 2;
                #pragma unroll
                for (int cc = 0; cc < 4; cc++) {
                    pm[r0 * PSTR + c0 + cc]       = acc[pp][cc].x + oxa[cc] + bcol[cc];
                    pm[(r0 + 1) * PSTR + c0 + cc] = acc[pp][cc].y + oya[cc] + bcol[cc];
                }
            }
        }
        BAR_GEMM();

        // ---------- Stage B: u,v (cw1), k-split 4, no emb prefix ----------
        #pragma unroll
        for (int pp = 0; pp < 3; pp++)
            #pragma unroll
            for (int cc = 0; cc < 4; cc++) acc[pp][cc] = make_float2(0.f, 0.f);
        {
            const int rowB = mloc * 448 + ks * 112;
            const float* wB = cw1 + rowB * HD + c0;
            const int xb0 = 32 + ks * 56;

            float4 w0a = *reinterpret_cast<const float4*>(wB);
            float4 w1a = *reinterpret_cast<const float4*>(wB + HD);
            float4 w0b = *reinterpret_cast<const float4*>(wB + 2 * HD);
            float4 w1b = *reinterpret_cast<const float4*>(wB + 3 * HD);

            #pragma unroll 2
            for (int it = 0; it < 54; it++) {
                float4 nw0 = *reinterpret_cast<const float4*>(wB + (2 * it + 4) * HD);
                float4 nw1 = *reinterpret_cast<const float4*>(wB + (2 * it + 5) * HD);
                float4 w0 = w0a, w1 = w1a;
                float4 xa  = xr0[xb0 + it];
                float4 xb4 = xr1[xb0 + it];
                float4 xc  = xr2[xb0 + it];
                PSTEP(acc[0], xa);
                PSTEP(acc[1], xb4);
                PSTEP(acc[2], xc);
                w0a = w0b; w1a = w1b;
                w0b = nw0; w1b = nw1;
            }
            #pragma unroll
            for (int t = 0; t < 2; t++) {
                float4 w0 = (t == 0) ? w0a : w0b;
                float4 w1 = (t == 0) ? w1a : w1b;
                int it = 54 + t;
                float4 xa  = xr0[xb0 + it];
                float4 xb4 = xr1[xb0 + it];
                float4 xc  = xr2[xb0 + it];
                PSTEP(acc[0], xa);
                PSTEP(acc[1], xb4);
                PSTEP(acc[2], xc);
            }
        }
        #pragma unroll
        for (int pp = 0; pp < 3; pp++)
            #pragma unroll
            for (int cc = 0; cc < 4; cc++) {
                unsigned long long v = *reinterpret_cast<unsigned long long*>(&acc[pp][cc]);
                unsigned long long o = __shfl_xor_sync(0xffffffffu, v, 16);
                float2 ov = *reinterpret_cast<float2*>(&o);
                acc[pp][cc].x += ov.x;
                acc[pp][cc].y += ov.y;
            }
        if (ksw == 1 && kh == 0) {
            float* gr = s->gred + (mloc * 4 + rg) * 384 + c0;
            #pragma unroll
            for (int pp = 0; pp < 3; pp++) {
                *reinterpret_cast<float4*>(gr + pp * 128) =
                    make_float4(acc[pp][0].x, acc[pp][1].x, acc[pp][2].x, acc[pp][3].x);
                *reinterpret_cast<float4*>(gr + pp * 128 + 64) =
                    make_float4(acc[pp][0].y, acc[pp][1].y, acc[pp][2].y, acc[pp][3].y);
            }
        }
        BAR_GEMM();
        if (ksw == 0 && kh == 0) {
            const float* gr = s->gred + (mloc * 4 + rg) * 384 + c0;
            float4 bb = make_float4(0.f, 0.f, 0.f, 0.f);
            if (mloc == 0) bb = *reinterpret_cast<const float4*>(cb1 + c0);
            float bcol[4] = {bb.x, bb.y, bb.z, bb.w};
            float* pm = s->proj[mloc];
            #pragma unroll
            for (int pp = 0; pp < 3; pp++) {
                float4 ox = *reinterpret_cast<const float4*>(gr + pp * 128);
                float4 oy = *reinterpret_cast<const float4*>(gr + pp * 128 + 64);
                float oxa[4] = {ox.x, ox.y, ox.z, ox.w};
                float oya[4] = {oy.x, oy.y, oy.z, oy.w};
                int r0 = (p0 + pp) * 2;
                #pragma unroll
                for (int cc = 0; cc < 4; cc++) {
                    pm[r0 * PSTR + c0 + cc]       = acc[pp][cc].x + oxa[cc] + bcol[cc];
                    pm[(r0 + 1) * PSTR + c0 + cc] = acc[pp][cc].y + oya[cc] + bcol[cc];
                }
            }
        }
    } else {
        // ====================== aux warps 16-19: stats + gram (thread-per-pair) ======================
        const int w4 = (tid >> 5) - 16;
        for (int i = w4; i < NN; i += 4) {
            const float4* xr = reinterpret_cast<const float4*>(s->xq + (i >> 1) * XQF);
            const int par = i & 1;
            float sm = 0.f, sq = 0.f;
            for (int kq = lane; kq < 224; kq += 32) {
                float4 v = xr[32 + kq];
                float a = par ? v.y : v.x;
                float c = par ? v.w : v.z;
                sm += a + c; sq += a * a + c * c;
            }
            sm = warpSum(sm); sq = warpSum(sq);
            if (lane == 0) {
                float mm  = sm / FF;
                float var = (sq - FF * mm * mm) / (FF - 1);
                var = fmaxf(var, 0.f);
                s->mu[i]   = mm;
                s->istd[i] = 1.0f / (sqrtf(var) + 1e-8f);
            }
        }
        BAR_AUX();
        // gram: thread-per-pair, 2 pairs interleaved (no shfl chains)
        {
            const int t = tid - 512;                 // 0..127; NUPD=253 so pair0 always valid
            const int  p0i   = t;
            const bool have1 = (t + 128) < NUPD;
            const int  p1i   = have1 ? t + 128 : 0;  // dummy -> computed, not written
            int code0 = s->plg[p0i];
            int code1 = s->plg[p1i];
            int i0 = code0 >> 5, j0 = code0 & 31;
            int i1 = code1 >> 5, j1 = code1 & 31;
            const float4* a0r = reinterpret_cast<const float4*>(s->xq + (i0 >> 1) * XQF) + 32;
            const float4* b0r = reinterpret_cast<const float4*>(s->xq + (j0 >> 1) * XQF) + 32;
            const float4* a1r = reinterpret_cast<const float4*>(s->xq + (i1 >> 1) * XQF) + 32;
            const float4* b1r = reinterpret_cast<const float4*>(s->xq + (j1 >> 1) * XQF) + 32;
            const int pa0 = i0 & 1, pb0 = j0 & 1, pa1 = i1 & 1, pb1 = j1 & 1;
            float dot0 = 0.f, dot1 = 0.f;
            #pragma unroll 4
            for (int kq = 0; kq < 224; kq++) {
                float4 a = a0r[kq];
                float4 c = b0r[kq];
                float av0 = pa0 ? a.y : a.x, av1 = pa0 ? a.w : a.z;
                float cv0 = pb0 ? c.y : c.x, cv1 = pb0 ? c.w : c.z;
                dot0 += av0 * cv0 + av1 * cv1;
                float4 d = a1r[kq];
                float4 e = b1r[kq];
                float dv0 = pa1 ? d.y : d.x, dv1 = pa1 ? d.w : d.z;
                float ev0 = pb1 ? e.y : e.x, ev1 = pb1 ? e.w : e.z;
                dot1 += dv0 * ev0 + dv1 * ev1;
            }
            float cv = fabsf((dot0 - (float)FF * s->mu[i0] * s->mu[j0]) * s->istd[i0] * s->istd[j0]) * (1.0f / FF);
            s->corrs[i0 * NN + j0] = cv;
            s->corrs[j0 * NN + i0] = cv;
            if (have1) {
                float cw = fabsf((dot1 - (float)FF * s->mu[i1] * s->mu[j1]) * s->istd[i1] * s->istd[j1]) * (1.0f / FF);
                s->corrs[i1 * NN + j1] = cw;
                s->corrs[j1 * NN + i1] = cw;
            }
        }
    }
    __syncthreads();   // publishes u,v,p,q + corrs to everyone

    // ====== tail: semantic MLP (tid<231) || corr MLP in-place (tid>=512) ======
    if (tid < NUP) {
        const float tthr = 1.0f / (1.0f + __expf(-thr[0]));
        int code = s->pl[tid];
        int i = code >> 5, j = code & 31;
        const float* pi = s->proj[2] + i * PSTR;
        const float* qj = s->proj[3] + j * PSTR;
        float sm = 0.f, sq = 0.f;
        #pragma unroll 4
        for (int c = 0; c < HD; c++) {
            float sv = pi[c] + qj[c];
            sm += sv; sq += sv * sv;
        }
        float muv  = sm * (1.0f / HD);
        float var  = sq * (1.0f / HD) - muv * muv;
        float rstd = rsqrtf(var + 1e-5f);
        float2 h2p[16];
        #pragma unroll
        for (int o = 0; o < 16; o++) h2p[o] = make_float2(s->sb2s[2 * o], s->sb2s[2 * o + 1]);
        #pragma unroll 2
        for (int c = 0; c < HD; c++) {
            float sv = pi[c] + qj[c];
            float h1 = fmaxf((sv - muv) * rstd * s->lngs[c] + s->lnbs[c], 0.f);
            float2 h1d = make_float2(h1, h1);
            const float4* wr = reinterpret_cast<const float4*>(s->sw2s + c * 36);
            #pragma unroll
            for (int o4 = 0; o4 < 8; o4++) {
                float4 w = wr[o4];
                fma2(h2p[2 * o4],     h1d, make_float2(w.x, w.y));
                fma2(h2p[2 * o4 + 1], h1d, make_float2(w.z, w.w));
            }
        }
        float z = sb3[0];
        #pragma unroll
        for (int o = 0; o < 16; o++) {
            z += fmaxf(h2p[o].x, 0.f) * s->sw3s[2 * o];
            z += fmaxf(h2p[o].y, 0.f) * s->sw3s[2 * o + 1];
        }
        float ws  = 1.0f / (1.0f + __expf(-z));
        float val = (ws > tthr) ? ws : 0.f;
        s->adjs[i * NN + j] = val;
        s->adjs[j * NN + i] = val;
    } else if (tid >= 512) {
        const float cb2v = cb2[0];
        for (int pidx = tid - 512; pidx < NPAIR; pidx += 128) {
            int i = pidx / NN, j = pidx - i * NN;
            const float* ui = s->proj[0] + i * PSTR;
            const float* vj = s->proj[1] + j * PSTR;
            float z = cb2v;
            #pragma unroll 4
            for (int c = 0; c < HD; c++)
                z += fmaxf(ui[c] + vj[c], 0.f) * s->cw2s[c];
            float wc = 1.0f / (1.0f + __expf(-z));
            s->corrs[pidx] *= wc;          // in-place: only this thread touches pidx
        }
    }
    __syncthreads();

    // ====================== final: fuse + store (trivial) ======================
    if (tid < NPAIR) {
        const float alpha = 1.0f / (1.0f + __expf(-alpha_p[0]));
        int i = tid / NN, j = tid - i * NN;
        float eye = (i == j) ? 1.0f : 0.0f;
        out[(size_t)b * NPAIR + tid] =
            alpha * s->corrs[tid] + (1.0f - alpha) * s->adjs[tid] + eye;
    }
}

extern "C" void kernel_launch(void* const* d_in, const int* in_sizes, int n_in,
                              void* d_out, int out_size) {
    const float* x       = (const float*)d_in[0];
    const float* cw1     = (const float*)d_in[1];
    const float* cb1     = (const float*)d_in[2];
    const float* cw2     = (const float*)d_in[3];
    const float* cb2     = (const float*)d_in[4];
    const float* emb     = (const float*)d_in[5];
    const float* sw1     = (const float*)d_in[6];
    const float* sb1     = (const float*)d_in[7];
    const float* ln_g    = (const float*)d_in[8];
    const float* ln_b    = (const float*)d_in[9];
    const float* sw2     = (const float*)d_in[10];
    const float* sb2     = (const float*)d_in[11];
    const float* sw3     = (const float*)d_in[12];
    const float* sb3     = (const float*)d_in[13];
    const float* thr     = (const float*)d_in[14];
    const float* alpha_p = (const float*)d_in[15];
    float* out = (float*)d_out;

    static bool attr_set = false;
    if (!attr_set) {
        cudaFuncSetAttribute(fused_kernel, cudaFuncAttributeMaxDynamicSharedMemorySize,
                             (int)sizeof(Smem));
        attr_set = true;
    }
    fused_kernel<<<BB, NT, sizeof(Smem)>>>(x, cw1, cb1, cw2, cb2, emb, sw1, sb1,
                                           ln_g, ln_b, sw2, sb2, sw3, sb3, thr, alpha_p, out);
}